// round 5
// baseline (speedup 1.0000x reference)
#include <cuda_runtime.h>
#include <cuda_bf16.h>

#define G      32
#define GC     (G * G * G)
#define GLO    (-6.0f)
#define H      (12.0f / G)
#define INVH   (G / 12.0f)
#define MAXB   4
#define MAXPTS 8192

// Static scratch (no allocations allowed).
__device__ int    g_cnt[2][MAXB][GC];        // counts, then reused as scatter cursors
__device__ int    g_start[2][MAXB][GC + 1];  // exclusive prefix (cell ranges)
__device__ float4 g_sorted[2][MAXB][MAXPTS]; // (x, y, z, 0.5*||p||^2) sorted by cell

__device__ __forceinline__ int cellCoord(float v) {
    int c = (int)floorf((v - GLO) * INVH);
    return min(max(c, 0), G - 1);
}

__global__ void k_zero(float* out) {
    int i = blockIdx.x * blockDim.x + threadIdx.x;
    int* p = &g_cnt[0][0][0];
    if (i < 2 * MAXB * GC) p[i] = 0;
    if (i == 0) out[0] = 0.0f;
}

__global__ void k_hist(const float* __restrict__ p1, const float* __restrict__ p2,
                       int B, int N, int M)
{
    int idx = blockIdx.x * blockDim.x + threadIdx.x;
    int tot0 = B * N;
    int cl, b; const float* p;
    if (idx < tot0) {
        cl = 0; b = idx / N; p = p1 + (size_t)idx * 3;
    } else if (idx < tot0 + B * M) {
        int j = idx - tot0;
        cl = 1; b = j / M; p = p2 + (size_t)j * 3;
    } else return;
    int cx = cellCoord(p[0]), cy = cellCoord(p[1]), cz = cellCoord(p[2]);
    atomicAdd(&g_cnt[cl][b][(cz * G + cy) * G + cx], 1);
}

// One block per (cloud, batch): exclusive scan of GC cells with 1024 threads x 32 cells.
__global__ __launch_bounds__(1024) void k_scan(int B) {
    int cl = blockIdx.x / B, b = blockIdx.x % B;
    const int* cnt = g_cnt[cl][b];
    int* st = g_start[cl][b];
    int* cur = g_cnt[cl][b];

    __shared__ int part[1024];
    int t = threadIdx.x;
    int base = t * 32;
    int loc[32];
    int s = 0;
#pragma unroll
    for (int i = 0; i < 32; i++) { loc[i] = s; s += cnt[base + i]; }
    part[t] = s;
    __syncthreads();
    for (int off = 1; off < 1024; off <<= 1) {
        int v = (t >= off) ? part[t - off] : 0;
        __syncthreads();
        part[t] += v;
        __syncthreads();
    }
    int prefix = (t > 0) ? part[t - 1] : 0;
    int total  = part[1023];
    __syncthreads();  // all reads of part done before cur (aliases cnt) is overwritten? cur writes below only
#pragma unroll
    for (int i = 0; i < 32; i++) {
        int v = prefix + loc[i];
        st[base + i] = v;
        cur[base + i] = v;   // cursor init for scatter (overwrites counts)
    }
    if (t == 1023) st[GC] = total;
}

__global__ void k_scatter(const float* __restrict__ p1, const float* __restrict__ p2,
                          int B, int N, int M)
{
    int idx = blockIdx.x * blockDim.x + threadIdx.x;
    int tot0 = B * N;
    int cl, b; const float* p;
    if (idx < tot0) {
        cl = 0; b = idx / N; p = p1 + (size_t)idx * 3;
    } else if (idx < tot0 + B * M) {
        int j = idx - tot0;
        cl = 1; b = j / M; p = p2 + (size_t)j * 3;
    } else return;
    float x = p[0], y = p[1], z = p[2];
    int cx = cellCoord(x), cy = cellCoord(y), cz = cellCoord(z);
    int cell = (cz * G + cy) * G + cx;
    int pos = atomicAdd(&g_cnt[cl][b][cell], 1);
    g_sorted[cl][b][pos] = make_float4(x, y, z, 0.5f * (x * x + y * y + z * z));
}

// One thread per (sorted) query; shell-expansion exact NN over the ref grid.
__global__ __launch_bounds__(256) void k_query(int B, int N, int M,
                                               float invBN, float invBM,
                                               float* __restrict__ out)
{
    const int dir = blockIdx.z;           // 0: p1->p2, 1: p2->p1
    const int b   = blockIdx.y;
    const int nq  = dir ? M : N;
    const int qi  = blockIdx.x * blockDim.x + threadIdx.x;

    float contrib = 0.0f;
    if (qi < nq) {
        const int qc = dir, rc = 1 - dir;
        float4 qv = g_sorted[qc][b][qi];
        const float qx = qv.x, qy = qv.y, qz = qv.z;
        const float q2 = 2.0f * qv.w;     // ||q||^2
        const int cx = cellCoord(qx), cy = cellCoord(qy), cz = cellCoord(qz);

        const float4* __restrict__ refs = g_sorted[rc][b];
        const int* __restrict__ st = g_start[rc][b];

        float smin = __int_as_float(0x7F800000);  // +inf; d = q2 + 2*smin

        auto cellCheck = [&](int ix, int iy, int iz) {
            float lo, dd, bd2;
            lo = GLO + ix * H; dd = fmaxf(fmaxf(lo - qx, qx - (lo + H)), 0.f); bd2 = dd * dd;
            lo = GLO + iy * H; dd = fmaxf(fmaxf(lo - qy, qy - (lo + H)), 0.f); bd2 = fmaf(dd, dd, bd2);
            lo = GLO + iz * H; dd = fmaxf(fmaxf(lo - qz, qz - (lo + H)), 0.f); bd2 = fmaf(dd, dd, bd2);
            float bestd = fmaxf(fmaf(2.0f, smin, q2), 0.0f);  // inf-safe
            if (bd2 < bestd) {
                int cell = (iz * G + iy) * G + ix;
                int s0 = __ldg(&st[cell]), s1 = __ldg(&st[cell + 1]);
                for (int i = s0; i < s1; i++) {
                    float4 rv = __ldg(&refs[i]);
                    float s = fmaf(rv.x, -qx, fmaf(rv.y, -qy, fmaf(rv.z, -qz, rv.w)));
                    smin = fminf(smin, s);
                }
            }
        };

        for (int r = 0; r < G; r++) {
            if (r >= 1) {
                // Exact lower bound on dist(q, any cell with Chebyshev offset >= r):
                // box-distance to the (r-1)-expanded home box (valid for any q).
                float bl, bh, dd, bd2;
                bl = GLO + (cx - (r - 1)) * H; bh = GLO + (cx + r) * H;
                dd = fmaxf(fmaxf(bl - qx, qx - bh), 0.f); bd2 = dd * dd;
                bl = GLO + (cy - (r - 1)) * H; bh = GLO + (cy + r) * H;
                dd = fmaxf(fmaxf(bl - qy, qy - bh), 0.f); bd2 = fmaf(dd, dd, bd2);
                bl = GLO + (cz - (r - 1)) * H; bh = GLO + (cz + r) * H;
                dd = fmaxf(fmaxf(bl - qz, qz - bh), 0.f); bd2 = fmaf(dd, dd, bd2);
                float bestd = fmaxf(fmaf(2.0f, smin, q2), 0.0f);
                if (bd2 >= bestd) break;
            }
            int x0 = max(cx - r, 0), x1 = min(cx + r, G - 1);
            int y0 = max(cy - r, 0), y1 = min(cy + r, G - 1);
            if (r == 0) {
                cellCheck(cx, cy, cz);
            } else {
                if (cz - r >= 0)
                    for (int yy = y0; yy <= y1; yy++)
                        for (int xx = x0; xx <= x1; xx++) cellCheck(xx, yy, cz - r);
                if (cz + r <= G - 1)
                    for (int yy = y0; yy <= y1; yy++)
                        for (int xx = x0; xx <= x1; xx++) cellCheck(xx, yy, cz + r);
                int zi0 = max(cz - r + 1, 0), zi1 = min(cz + r - 1, G - 1);
                for (int zz = zi0; zz <= zi1; zz++) {
                    if (cy - r >= 0)
                        for (int xx = x0; xx <= x1; xx++) cellCheck(xx, cy - r, zz);
                    if (cy + r <= G - 1)
                        for (int xx = x0; xx <= x1; xx++) cellCheck(xx, cy + r, zz);
                    int yi0 = max(cy - r + 1, 0), yi1 = min(cy + r - 1, G - 1);
                    if (cx - r >= 0)
                        for (int yy = yi0; yy <= yi1; yy++) cellCheck(cx - r, yy, zz);
                    if (cx + r <= G - 1)
                        for (int yy = yi0; yy <= yi1; yy++) cellCheck(cx + r, yy, zz);
                }
            }
        }
        float d = fmaxf(fmaf(2.0f, smin, q2), 0.0f);
        contrib = d * (dir ? invBM : invBN);
    }

    __shared__ float ssum[256];
    ssum[threadIdx.x] = contrib;
    __syncthreads();
    for (int s = blockDim.x / 2; s > 0; s >>= 1) {
        if (threadIdx.x < s) ssum[threadIdx.x] += ssum[threadIdx.x + s];
        __syncthreads();
    }
    if (threadIdx.x == 0) atomicAdd(out, ssum[0]);
}

extern "C" void kernel_launch(void* const* d_in, const int* in_sizes, int n_in,
                              void* d_out, int out_size)
{
    const float* p1 = (const float*)d_in[0];
    const float* p2 = (const float*)d_in[1];

    const int B = 4;
    const int N = in_sizes[0] / (B * 3);
    const int M = in_sizes[1] / (B * 3);

    k_zero<<<(2 * MAXB * GC + 255) / 256, 256>>>((float*)d_out);

    const int totPts = B * (N + M);
    k_hist<<<(totPts + 255) / 256, 256>>>(p1, p2, B, N, M);

    k_scan<<<2 * B, 1024>>>(B);

    k_scatter<<<(totPts + 255) / 256, 256>>>(p1, p2, B, N, M);

    const int maxNM = N > M ? N : M;
    dim3 qgrid((maxNM + 255) / 256, B, 2);
    k_query<<<qgrid, 256>>>(B, N, M,
                            1.0f / (float)(B * N), 1.0f / (float)(B * M),
                            (float*)d_out);
}

// round 6
// speedup vs baseline: 6.8289x; 6.8289x over previous
#include <cuda_runtime.h>
#include <cuda_bf16.h>

#define G      32
#define GC     (G * G * G)
#define GLO    (-6.0f)
#define H      (12.0f / G)
#define INVH   (G / 12.0f)
#define MAXB   4
#define MAXPTS 8192
#define FULLM  0xFFFFFFFFu

// Static scratch (no allocations allowed).
__device__ int    g_cnt[2][MAXB][GC];        // counts, then reused as scatter cursors
__device__ int    g_start[2][MAXB][GC + 1];  // exclusive prefix (cell ranges)
__device__ float4 g_sorted[2][MAXB][MAXPTS]; // (x, y, z, 0.5*||p||^2) sorted by cell

__device__ __forceinline__ int cellCoord(float v) {
    int c = (int)floorf((v - GLO) * INVH);
    return min(max(c, 0), G - 1);
}

__global__ void k_zero(float* out) {
    int i = blockIdx.x * blockDim.x + threadIdx.x;
    int* p = &g_cnt[0][0][0];
    if (i < 2 * MAXB * GC) p[i] = 0;
    if (i == 0) out[0] = 0.0f;
}

__global__ void k_hist(const float* __restrict__ p1, const float* __restrict__ p2,
                       int B, int N, int M)
{
    int idx = blockIdx.x * blockDim.x + threadIdx.x;
    int tot0 = B * N;
    int cl, b; const float* p;
    if (idx < tot0) {
        cl = 0; b = idx / N; p = p1 + (size_t)idx * 3;
    } else if (idx < tot0 + B * M) {
        int j = idx - tot0;
        cl = 1; b = j / M; p = p2 + (size_t)j * 3;
    } else return;
    int cx = cellCoord(p[0]), cy = cellCoord(p[1]), cz = cellCoord(p[2]);
    atomicAdd(&g_cnt[cl][b][(cz * G + cy) * G + cx], 1);
}

// One block per (cloud, batch): exclusive scan of GC cells with 1024 threads x 32 cells.
__global__ __launch_bounds__(1024) void k_scan(int B) {
    int cl = blockIdx.x / B, b = blockIdx.x % B;
    const int* cnt = g_cnt[cl][b];
    int* st = g_start[cl][b];
    int* cur = g_cnt[cl][b];

    __shared__ int part[1024];
    int t = threadIdx.x;
    int base = t * 32;
    int loc[32];
    int s = 0;
#pragma unroll
    for (int i = 0; i < 32; i++) { loc[i] = s; s += cnt[base + i]; }
    part[t] = s;
    __syncthreads();
    for (int off = 1; off < 1024; off <<= 1) {
        int v = (t >= off) ? part[t - off] : 0;
        __syncthreads();
        part[t] += v;
        __syncthreads();
    }
    int prefix = (t > 0) ? part[t - 1] : 0;
    int total  = part[1023];
#pragma unroll
    for (int i = 0; i < 32; i++) {
        int v = prefix + loc[i];
        st[base + i] = v;
        cur[base + i] = v;   // cursor init for scatter (overwrites counts)
    }
    if (t == 1023) st[GC] = total;
}

__global__ void k_scatter(const float* __restrict__ p1, const float* __restrict__ p2,
                          int B, int N, int M)
{
    int idx = blockIdx.x * blockDim.x + threadIdx.x;
    int tot0 = B * N;
    int cl, b; const float* p;
    if (idx < tot0) {
        cl = 0; b = idx / N; p = p1 + (size_t)idx * 3;
    } else if (idx < tot0 + B * M) {
        int j = idx - tot0;
        cl = 1; b = j / M; p = p2 + (size_t)j * 3;
    } else return;
    float x = p[0], y = p[1], z = p[2];
    int cx = cellCoord(x), cy = cellCoord(y), cz = cellCoord(z);
    int cell = (cz * G + cy) * G + cx;
    int pos = atomicAdd(&g_cnt[cl][b][cell], 1);
    g_sorted[cl][b][pos] = make_float4(x, y, z, 0.5f * (x * x + y * y + z * z));
}

// Warp-coherent exact NN: each warp takes 32 consecutive cell-sorted queries,
// walks shells of the warp's union cell box with uniform control flow.
// Broadcast loads; every lane min-updates on every loaded point (always safe).
__global__ __launch_bounds__(256) void k_query(int B, int N, int M,
                                               float invBN, float invBM,
                                               float* __restrict__ out)
{
    const int dir = blockIdx.z;           // 0: p1->p2, 1: p2->p1
    const int b   = blockIdx.y;
    const int nq  = dir ? M : N;
    const int qi  = blockIdx.x * blockDim.x + threadIdx.x;
    const int qic = min(qi, nq - 1);
    const float INFv = __int_as_float(0x7F800000);

    const int qc = dir, rc = 1 - dir;
    float4 qv = g_sorted[qc][b][qic];
    const float qx = qv.x, qy = qv.y, qz = qv.z;
    const float q2 = 2.0f * qv.w;         // ||q||^2
    const int cx = cellCoord(qx), cy = cellCoord(qy), cz = cellCoord(qz);

    // Warp union box of home cells.
    const int bx0 = __reduce_min_sync(FULLM, cx), bx1 = __reduce_max_sync(FULLM, cx);
    const int by0 = __reduce_min_sync(FULLM, cy), by1 = __reduce_max_sync(FULLM, cy);
    const int bz0 = __reduce_min_sync(FULLM, cz), bz1 = __reduce_max_sync(FULLM, cz);

    const float4* __restrict__ refs = g_sorted[rc][b];
    const int* __restrict__ st = g_start[rc][b];

    float smin = INFv;
    bool done = false;

    auto visit = [&](int ix, int iy, int iz) {
        float lo, dd, bd2;
        lo = GLO + ix * H; dd = fmaxf(fmaxf(lo - qx, qx - (lo + H)), 0.f); bd2 = dd * dd;
        lo = GLO + iy * H; dd = fmaxf(fmaxf(lo - qy, qy - (lo + H)), 0.f); bd2 = fmaf(dd, dd, bd2);
        lo = GLO + iz * H; dd = fmaxf(fmaxf(lo - qz, qz - (lo + H)), 0.f); bd2 = fmaf(dd, dd, bd2);
        float bestd = fmaxf(fmaf(2.0f, smin, q2), 0.0f);
        bool want = (!done) && (bd2 < bestd);
        if (__any_sync(FULLM, want)) {
            int cell = (iz * G + iy) * G + ix;
            int s0 = __ldg(&st[cell]), s1 = __ldg(&st[cell + 1]);
            for (int i = s0; i < s1; i++) {
                float4 rv = __ldg(&refs[i]);
                float sv = fmaf(rv.x, -qx, fmaf(rv.y, -qy, fmaf(rv.z, -qz, rv.w)));
                smin = fminf(smin, sv);
            }
        }
    };

    for (int r = 0; r < G; r++) {
        if (r >= 1) {
            // Lane done when distance to EXTERIOR of box expanded by (r-1)
            // already exceeds current best (faces at grid edge -> +inf).
            int ex0 = bx0 - (r - 1), ex1 = bx1 + (r - 1);
            int ey0 = by0 - (r - 1), ey1 = by1 + (r - 1);
            int ez0 = bz0 - (r - 1), ez1 = bz1 + (r - 1);
            float d0 = (ex0 <= 0)     ? INFv : (qx - (GLO + ex0 * H));
            float d1 = (ex1 >= G - 1) ? INFv : ((GLO + (ex1 + 1) * H) - qx);
            float d2 = (ey0 <= 0)     ? INFv : (qy - (GLO + ey0 * H));
            float d3 = (ey1 >= G - 1) ? INFv : ((GLO + (ey1 + 1) * H) - qy);
            float d4 = (ez0 <= 0)     ? INFv : (qz - (GLO + ez0 * H));
            float d5 = (ez1 >= G - 1) ? INFv : ((GLO + (ez1 + 1) * H) - qz);
            float bd = fminf(fminf(fminf(d0, d1), fminf(d2, d3)), fminf(d4, d5));
            float bestd = fmaxf(fmaf(2.0f, smin, q2), 0.0f);
            done = done || (bd * bd >= bestd);
            if (__all_sync(FULLM, done)) break;
        }
        int x0 = max(bx0 - r, 0), x1 = min(bx1 + r, G - 1);
        int y0 = max(by0 - r, 0), y1 = min(by1 + r, G - 1);
        if (r == 0) {
            for (int zz = bz0; zz <= bz1; zz++)
                for (int yy = by0; yy <= by1; yy++)
                    for (int xx = bx0; xx <= bx1; xx++) visit(xx, yy, zz);
        } else {
            if (bz0 - r >= 0)
                for (int yy = y0; yy <= y1; yy++)
                    for (int xx = x0; xx <= x1; xx++) visit(xx, yy, bz0 - r);
            if (bz1 + r <= G - 1)
                for (int yy = y0; yy <= y1; yy++)
                    for (int xx = x0; xx <= x1; xx++) visit(xx, yy, bz1 + r);
            int zi0 = max(bz0 - r + 1, 0), zi1 = min(bz1 + r - 1, G - 1);
            for (int zz = zi0; zz <= zi1; zz++) {
                if (by0 - r >= 0)
                    for (int xx = x0; xx <= x1; xx++) visit(xx, by0 - r, zz);
                if (by1 + r <= G - 1)
                    for (int xx = x0; xx <= x1; xx++) visit(xx, by1 + r, zz);
                int yi0 = max(by0 - r + 1, 0), yi1 = min(by1 + r - 1, G - 1);
                if (bx0 - r >= 0)
                    for (int yy = yi0; yy <= yi1; yy++) visit(bx0 - r, yy, zz);
                if (bx1 + r <= G - 1)
                    for (int yy = yi0; yy <= yi1; yy++) visit(bx1 + r, yy, zz);
            }
        }
    }

    float d = fmaxf(fmaf(2.0f, smin, q2), 0.0f);
    float contrib = (qi < nq) ? d * (dir ? invBM : invBN) : 0.0f;

    __shared__ float ssum[256];
    ssum[threadIdx.x] = contrib;
    __syncthreads();
    for (int s = blockDim.x / 2; s > 0; s >>= 1) {
        if (threadIdx.x < s) ssum[threadIdx.x] += ssum[threadIdx.x + s];
        __syncthreads();
    }
    if (threadIdx.x == 0) atomicAdd(out, ssum[0]);
}

extern "C" void kernel_launch(void* const* d_in, const int* in_sizes, int n_in,
                              void* d_out, int out_size)
{
    const float* p1 = (const float*)d_in[0];
    const float* p2 = (const float*)d_in[1];

    const int B = 4;
    const int N = in_sizes[0] / (B * 3);
    const int M = in_sizes[1] / (B * 3);

    k_zero<<<(2 * MAXB * GC + 255) / 256, 256>>>((float*)d_out);

    const int totPts = B * (N + M);
    k_hist<<<(totPts + 255) / 256, 256>>>(p1, p2, B, N, M);

    k_scan<<<2 * B, 1024>>>(B);

    k_scatter<<<(totPts + 255) / 256, 256>>>(p1, p2, B, N, M);

    const int maxNM = N > M ? N : M;
    dim3 qgrid((maxNM + 255) / 256, B, 2);
    k_query<<<qgrid, 256>>>(B, N, M,
                            1.0f / (float)(B * N), 1.0f / (float)(B * M),
                            (float*)d_out);
}

// round 7
// speedup vs baseline: 10.1424x; 1.4852x over previous
#include <cuda_runtime.h>
#include <cuda_bf16.h>

#define NB     512
#define GLO    (-6.0f)
#define BW     (12.0f / NB)
#define INVW   (NB / 12.0f)
#define MAXB   4
#define MAXPTS 8192
#define MAXPR  (MAXPTS / 2)
#define FULLM  0xFFFFFFFFu

// Static scratch (no device allocations allowed).
__device__ int    g_cnt[2][MAXB][NB];        // counts -> scatter cursors
__device__ int    g_start[2][MAXB][NB + 1];  // exclusive prefix (bin ranges)
// Pair-packed, x-bin-sorted points: A = {x0,x1,y0,y1}, B = {z0,z1,w0,w1}, w = 0.5*||p||^2
__device__ float4 g_sA[2][MAXB][MAXPR];
__device__ float4 g_sB[2][MAXB][MAXPR];

__device__ __forceinline__ int binOf(float x) {
    int c = (int)floorf((x - GLO) * INVW);
    return min(max(c, 0), NB - 1);
}

// ---- packed f32x2 helpers ----
__device__ __forceinline__ unsigned long long pk2(float lo, float hi) {
    unsigned long long v;
    asm("mov.b64 %0, {%1, %2};" : "=l"(v) : "f"(lo), "f"(hi));
    return v;
}
__device__ __forceinline__ unsigned long long fma2(unsigned long long a,
                                                   unsigned long long b,
                                                   unsigned long long c) {
    unsigned long long d;
    asm("fma.rn.f32x2 %0, %1, %2, %3;" : "=l"(d) : "l"(a), "l"(b), "l"(c));
    return d;
}
__device__ __forceinline__ void unpk2(unsigned long long v, float& lo, float& hi) {
    asm("mov.b64 {%0, %1}, %2;" : "=f"(lo), "=f"(hi) : "l"(v));
}

__global__ void k_zero(float* out) {
    int i = blockIdx.x * blockDim.x + threadIdx.x;
    int* c = &g_cnt[0][0][0];
    if (i < 2 * MAXB * NB) c[i] = 0;
    // Pad all pair slots: w = +inf so stale halves can never win a min.
    if (i < 2 * MAXB * MAXPR) {
        float4* A = &g_sA[0][0][0];
        float4* B = &g_sB[0][0][0];
        A[i] = make_float4(0.f, 0.f, 0.f, 0.f);
        float inf = __int_as_float(0x7F800000);
        B[i] = make_float4(0.f, 0.f, inf, inf);
    }
    if (i == 0) out[0] = 0.0f;
}

__global__ void k_hist(const float* __restrict__ p1, const float* __restrict__ p2,
                       int B, int N, int M)
{
    int idx = blockIdx.x * blockDim.x + threadIdx.x;
    int tot0 = B * N;
    int cl, b; const float* p;
    if (idx < tot0) {
        cl = 0; b = idx / N; p = p1 + (size_t)idx * 3;
    } else if (idx < tot0 + B * M) {
        int j = idx - tot0;
        cl = 1; b = j / M; p = p2 + (size_t)j * 3;
    } else return;
    atomicAdd(&g_cnt[cl][b][binOf(p[0])], 1);
}

// One block per (cloud,batch): NB-thread scan.
__global__ __launch_bounds__(NB) void k_scan(int B) {
    int cl = blockIdx.x / B, b = blockIdx.x % B;
    __shared__ int sh[NB];
    int t = threadIdx.x;
    int c = g_cnt[cl][b][t];
    sh[t] = c;
    __syncthreads();
    for (int off = 1; off < NB; off <<= 1) {
        int v = (t >= off) ? sh[t - off] : 0;
        __syncthreads();
        sh[t] += v;
        __syncthreads();
    }
    int excl = sh[t] - c;
    g_start[cl][b][t] = excl;
    g_cnt[cl][b][t] = excl;            // cursor for scatter
    if (t == NB - 1) g_start[cl][b][NB] = sh[t];
}

__global__ void k_scatter(const float* __restrict__ p1, const float* __restrict__ p2,
                          int B, int N, int M)
{
    int idx = blockIdx.x * blockDim.x + threadIdx.x;
    int tot0 = B * N;
    int cl, b; const float* p;
    if (idx < tot0) {
        cl = 0; b = idx / N; p = p1 + (size_t)idx * 3;
    } else if (idx < tot0 + B * M) {
        int j = idx - tot0;
        cl = 1; b = j / M; p = p2 + (size_t)j * 3;
    } else return;
    float x = p[0], y = p[1], z = p[2];
    int pos = atomicAdd(&g_cnt[cl][b][binOf(x)], 1);
    int pr = pos >> 1, h = pos & 1;
    float* A  = (float*)&g_sA[cl][b][pr];
    float* Bp = (float*)&g_sB[cl][b][pr];
    A[h] = x;  A[2 + h] = y;
    Bp[h] = z; Bp[2 + h] = 0.5f * (x * x + y * y + z * z);
}

// Exact NN via 1D x-window expansion; inner loop = packed f32x2 brute force
// over the warp-uniform candidate window. Self-balancing: the window holds
// O(32 + rings) points in any density regime.
__global__ __launch_bounds__(256) void k_query(int B, int N, int M,
                                               float invBN, float invBM,
                                               float* __restrict__ out)
{
    const int dir = blockIdx.z;           // 0: p1->p2, 1: p2->p1
    const int b   = blockIdx.y;
    const int nq  = dir ? M : N;
    const int qi  = blockIdx.x * blockDim.x + threadIdx.x;
    const int qic = min(qi, nq - 1);
    const float INFv = __int_as_float(0x7F800000);

    const int qc = dir, rc = 1 - dir;

    // Load own (sorted) query point from the packed arrays.
    float4 qa = g_sA[qc][b][qic >> 1];
    float4 qb = g_sB[qc][b][qic >> 1];
    const int h = qic & 1;
    const float qx = h ? qa.y : qa.x;
    const float qy = h ? qa.w : qa.z;
    const float qz = h ? qb.y : qb.x;
    const float q2 = 2.0f * (h ? qb.w : qb.z);  // ||q||^2

    const int bq  = binOf(qx);
    const int wb0 = __reduce_min_sync(FULLM, bq);
    const int wb1 = __reduce_max_sync(FULLM, bq);

    const float4* __restrict__ A  = g_sA[rc][b];
    const float4* __restrict__ Bv = g_sB[rc][b];
    const int* __restrict__ st = g_start[rc][b];

    const unsigned long long nqx = pk2(-qx, -qx);
    const unsigned long long nqy = pk2(-qy, -qy);
    const unsigned long long nqz = pk2(-qz, -qz);
    float mnA = INFv, mnB = INFv;

    auto scanBin = [&](int bin) {
        int s0 = __ldg(&st[bin]);
        int s1 = __ldg(&st[bin + 1]);
        int p0 = s0 >> 1, p1 = (s1 + 1) >> 1;   // pair-rounded: extra real pts are safe
        for (int p = p0; p < p1; p++) {
            ulonglong2 av = __ldg((const ulonglong2*)(A + p));   // {x0,x1},{y0,y1}
            ulonglong2 cv = __ldg((const ulonglong2*)(Bv + p));  // {z0,z1},{w0,w1}
            unsigned long long s = fma2(av.x, nqx,
                                   fma2(av.y, nqy,
                                   fma2(cv.x, nqz, cv.y)));
            float lo, hi;
            unpk2(s, lo, hi);
            mnA = fminf(mnA, lo);
            mnB = fminf(mnB, hi);
        }
    };

    // d = 0: warp's home window.
    for (int bin = wb0; bin <= wb1; bin++) scanBin(bin);

    // Two-sided ring expansion with exact per-lane termination.
    for (int d = 1; d <= NB; d++) {
        // Rings through d-1 complete: unscanned left bins <= wb0-d have x < Tl;
        // unscanned right bins >= wb1+d have x >= Tr.
        float bestd = fmaxf(fmaf(2.0f, fminf(mnA, mnB), q2), 0.0f);
        float dxl = (wb0 - d < 0)       ? INFv : (qx - (GLO + (wb0 - d + 1) * BW));
        float dxr = (wb1 + d > NB - 1)  ? INFv : ((GLO + (wb1 + d) * BW) - qx);
        float dmin = fminf(dxl, dxr);
        if (__all_sync(FULLM, dmin * dmin >= bestd)) break;
        int lb = wb0 - d, rb = wb1 + d;
        if (lb >= 0) scanBin(lb);
        if (rb <= NB - 1) scanBin(rb);
    }

    float dnn = fmaxf(fmaf(2.0f, fminf(mnA, mnB), q2), 0.0f);
    float contrib = (qi < nq) ? dnn * (dir ? invBM : invBN) : 0.0f;

    __shared__ float ssum[256];
    ssum[threadIdx.x] = contrib;
    __syncthreads();
    for (int s = blockDim.x / 2; s > 0; s >>= 1) {
        if (threadIdx.x < s) ssum[threadIdx.x] += ssum[threadIdx.x + s];
        __syncthreads();
    }
    if (threadIdx.x == 0) atomicAdd(out, ssum[0]);
}

extern "C" void kernel_launch(void* const* d_in, const int* in_sizes, int n_in,
                              void* d_out, int out_size)
{
    const float* p1 = (const float*)d_in[0];
    const float* p2 = (const float*)d_in[1];

    const int B = 4;
    const int N = in_sizes[0] / (B * 3);
    const int M = in_sizes[1] / (B * 3);

    const int zeroN = 2 * MAXB * MAXPR;
    k_zero<<<(zeroN + 255) / 256, 256>>>((float*)d_out);

    const int totPts = B * (N + M);
    k_hist<<<(totPts + 255) / 256, 256>>>(p1, p2, B, N, M);

    k_scan<<<2 * B, NB>>>(B);

    k_scatter<<<(totPts + 255) / 256, 256>>>(p1, p2, B, N, M);

    const int maxNM = N > M ? N : M;
    dim3 qgrid((maxNM + 255) / 256, B, 2);
    k_query<<<qgrid, 256>>>(B, N, M,
                            1.0f / (float)(B * N), 1.0f / (float)(B * M),
                            (float*)d_out);
}

// round 8
// speedup vs baseline: 12.2128x; 1.2041x over previous
#include <cuda_runtime.h>
#include <cuda_bf16.h>

#define NB     512
#define GLO    (-6.0f)
#define BW     (12.0f / NB)
#define INVW   (NB / 12.0f)
#define MAXB   4
#define MAXPTS 8192
#define MAXPR  (MAXPTS / 2)
#define FULLM  0xFFFFFFFFu

// Static scratch (no device allocations allowed).
__device__ int    g_cnt[2][MAXB][NB];        // counts -> scatter cursors
__device__ int    g_start[2][MAXB][NB + 1];  // exclusive prefix (bin ranges)
// Pair-packed, x-bin-sorted points: A = {x0,x1,y0,y1}, B = {z0,z1,w0,w1}, w = 0.5*||p||^2
__device__ float4 g_sA[2][MAXB][MAXPR];
__device__ float4 g_sB[2][MAXB][MAXPR];

__device__ __forceinline__ int binOf(float x) {
    int c = (int)floorf((x - GLO) * INVW);
    return min(max(c, 0), NB - 1);
}

// ---- packed f32x2 helpers ----
__device__ __forceinline__ unsigned long long pk2(float lo, float hi) {
    unsigned long long v;
    asm("mov.b64 %0, {%1, %2};" : "=l"(v) : "f"(lo), "f"(hi));
    return v;
}
__device__ __forceinline__ unsigned long long fma2(unsigned long long a,
                                                   unsigned long long b,
                                                   unsigned long long c) {
    unsigned long long d;
    asm("fma.rn.f32x2 %0, %1, %2, %3;" : "=l"(d) : "l"(a), "l"(b), "l"(c));
    return d;
}
__device__ __forceinline__ void unpk2(unsigned long long v, float& lo, float& hi) {
    asm("mov.b64 {%0, %1}, %2;" : "=f"(lo), "=f"(hi) : "l"(v));
}

__global__ void k_zero(float* out) {
    int i = blockIdx.x * blockDim.x + threadIdx.x;
    int* c = &g_cnt[0][0][0];
    if (i < 2 * MAXB * NB) c[i] = 0;
    if (i == 0) out[0] = 0.0f;
}

__global__ void k_hist(const float* __restrict__ p1, const float* __restrict__ p2,
                       int B, int N, int M)
{
    int idx = blockIdx.x * blockDim.x + threadIdx.x;
    int tot0 = B * N;
    int cl, b; const float* p;
    if (idx < tot0) {
        cl = 0; b = idx / N; p = p1 + (size_t)idx * 3;
    } else if (idx < tot0 + B * M) {
        int j = idx - tot0;
        cl = 1; b = j / M; p = p2 + (size_t)j * 3;
    } else return;
    atomicAdd(&g_cnt[cl][b][binOf(p[0])], 1);
}

// One block per (cloud,batch): NB-thread scan. Also writes the odd-total pad.
__global__ __launch_bounds__(NB) void k_scan(int B) {
    int cl = blockIdx.x / B, b = blockIdx.x % B;
    __shared__ int sh[NB];
    int t = threadIdx.x;
    int c = g_cnt[cl][b][t];
    sh[t] = c;
    __syncthreads();
    for (int off = 1; off < NB; off <<= 1) {
        int v = (t >= off) ? sh[t - off] : 0;
        __syncthreads();
        sh[t] += v;
        __syncthreads();
    }
    int excl = sh[t] - c;
    g_start[cl][b][t] = excl;
    g_cnt[cl][b][t] = excl;            // cursor for scatter
    if (t == NB - 1) {
        int total = sh[t];
        g_start[cl][b][NB] = total;
        if (total & 1) {
            // Pad the unwritten odd half: w1 = +inf => that half's score is
            // +inf (or NaN if stale x is NaN, which fminf ignores). Safe.
            g_sB[cl][b][total >> 1].w = __int_as_float(0x7F800000);
        }
    }
}

__global__ void k_scatter(const float* __restrict__ p1, const float* __restrict__ p2,
                          int B, int N, int M)
{
    int idx = blockIdx.x * blockDim.x + threadIdx.x;
    int tot0 = B * N;
    int cl, b; const float* p;
    if (idx < tot0) {
        cl = 0; b = idx / N; p = p1 + (size_t)idx * 3;
    } else if (idx < tot0 + B * M) {
        int j = idx - tot0;
        cl = 1; b = j / M; p = p2 + (size_t)j * 3;
    } else return;
    float x = p[0], y = p[1], z = p[2];
    int pos = atomicAdd(&g_cnt[cl][b][binOf(x)], 1);
    int pr = pos >> 1, h = pos & 1;
    float* A  = (float*)&g_sA[cl][b][pr];
    float* Bp = (float*)&g_sB[cl][b][pr];
    A[h] = x;  A[2 + h] = y;
    Bp[h] = z; Bp[2 + h] = 0.5f * (x * x + y * y + z * z);
}

// Two-phase exact NN:
//  A) scan warp home bins (expand only until every lane has a finite bound)
//  B) one contiguous packed-FFMA2 stream over the bound-derived x-window.
__global__ __launch_bounds__(256) void k_query(int B, int N, int M,
                                               float invBN, float invBM,
                                               float* __restrict__ out)
{
    const int dir = blockIdx.z;           // 0: p1->p2, 1: p2->p1
    const int b   = blockIdx.y;
    const int nq  = dir ? M : N;
    const int qi  = blockIdx.x * blockDim.x + threadIdx.x;
    const int qic = min(qi, nq - 1);
    const float INFv = __int_as_float(0x7F800000);

    const int qc = dir, rc = 1 - dir;

    float4 qa = g_sA[qc][b][qic >> 1];
    float4 qb = g_sB[qc][b][qic >> 1];
    const int h = qic & 1;
    const float qx = h ? qa.y : qa.x;
    const float qy = h ? qa.w : qa.z;
    const float qz = h ? qb.y : qb.x;
    const float q2 = 2.0f * (h ? qb.w : qb.z);  // ||q||^2

    const int bq  = binOf(qx);
    const int wb0 = __reduce_min_sync(FULLM, bq);
    const int wb1 = __reduce_max_sync(FULLM, bq);

    const float4* __restrict__ A  = g_sA[rc][b];
    const float4* __restrict__ Bv = g_sB[rc][b];
    const int* __restrict__ st = g_start[rc][b];

    const unsigned long long nqx = pk2(-qx, -qx);
    const unsigned long long nqy = pk2(-qy, -qy);
    const unsigned long long nqz = pk2(-qz, -qz);
    float mnA = INFv, mnB = INFv;

    auto scanPairs = [&](int p0, int p1) {
#pragma unroll 4
        for (int p = p0; p < p1; p++) {
            ulonglong2 av = __ldg((const ulonglong2*)(A + p));   // {x0,x1},{y0,y1}
            ulonglong2 cv = __ldg((const ulonglong2*)(Bv + p));  // {z0,z1},{w0,w1}
            unsigned long long s = fma2(av.x, nqx,
                                   fma2(av.y, nqy,
                                   fma2(cv.x, nqz, cv.y)));
            float lo, hi;
            unpk2(s, lo, hi);
            mnA = fminf(mnA, lo);
            mnB = fminf(mnB, hi);
        }
    };

    // ---- Phase A: home window, expand only until all lanes have a bound ----
    int sLo = wb0, sHi = wb1;
    scanPairs(__ldg(&st[wb0]) >> 1, (__ldg(&st[wb1 + 1]) + 1) >> 1);
    for (int d = 1; d <= NB; d++) {
        bool fin = (fminf(mnA, mnB) < INFv);
        if (__all_sync(FULLM, fin)) break;
        int lb = wb0 - d, rb = wb1 + d;
        if (lb >= 0) { scanPairs(__ldg(&st[lb]) >> 1, (__ldg(&st[lb + 1]) + 1) >> 1); sLo = lb; }
        if (rb < NB) { scanPairs(__ldg(&st[rb]) >> 1, (__ldg(&st[rb + 1]) + 1) >> 1); sHi = rb; }
        if (lb < 0 && rb >= NB) break;
    }

    // ---- Phase B: exact window from the bound; one contiguous stream ----
    {
        float bestd = fmaxf(fmaf(2.0f, fminf(mnA, mnB), q2), 0.0f);
        float r = sqrtf(bestd);
        float wlo = qx - r, whi = qx + r;
#pragma unroll
        for (int o = 16; o > 0; o >>= 1) {
            wlo = fminf(wlo, __shfl_xor_sync(FULLM, wlo, o));
            whi = fmaxf(whi, __shfl_xor_sync(FULLM, whi, o));
        }
        int binLo = binOf(wlo);
        int binHi = binOf(whi);
        if (binLo < sLo)   // left segment: bins [binLo, sLo)
            scanPairs(__ldg(&st[binLo]) >> 1, (__ldg(&st[sLo]) + 1) >> 1);
        if (binHi > sHi)   // right segment: bins (sHi, binHi]
            scanPairs(__ldg(&st[sHi + 1]) >> 1, (__ldg(&st[binHi + 1]) + 1) >> 1);
    }

    float dnn = fmaxf(fmaf(2.0f, fminf(mnA, mnB), q2), 0.0f);
    float contrib = (qi < nq) ? dnn * (dir ? invBM : invBN) : 0.0f;

    __shared__ float ssum[256];
    ssum[threadIdx.x] = contrib;
    __syncthreads();
    for (int s = blockDim.x / 2; s > 0; s >>= 1) {
        if (threadIdx.x < s) ssum[threadIdx.x] += ssum[threadIdx.x + s];
        __syncthreads();
    }
    if (threadIdx.x == 0) atomicAdd(out, ssum[0]);
}

extern "C" void kernel_launch(void* const* d_in, const int* in_sizes, int n_in,
                              void* d_out, int out_size)
{
    const float* p1 = (const float*)d_in[0];
    const float* p2 = (const float*)d_in[1];

    const int B = 4;
    const int N = in_sizes[0] / (B * 3);
    const int M = in_sizes[1] / (B * 3);

    k_zero<<<(2 * MAXB * NB + 255) / 256, 256>>>((float*)d_out);

    const int totPts = B * (N + M);
    k_hist<<<(totPts + 255) / 256, 256>>>(p1, p2, B, N, M);

    k_scan<<<2 * B, NB>>>(B);

    k_scatter<<<(totPts + 255) / 256, 256>>>(p1, p2, B, N, M);

    const int maxNM = N > M ? N : M;
    dim3 qgrid((maxNM + 255) / 256, B, 2);
    k_query<<<qgrid, 256>>>(B, N, M,
                            1.0f / (float)(B * N), 1.0f / (float)(B * M),
                            (float*)d_out);
}